// round 16
// baseline (speedup 1.0000x reference)
#include <cuda_runtime.h>
#include <cuda_fp16.h>
#include <math.h>

#define S_LEN 2048
#define HID   2048
#define NHEAD 16
#define HD    128
#define MROWS 4096
#define SCALE 0.08838834764831845f

// ---------------------------------------------------------------------------
// Global scratch
// ---------------------------------------------------------------------------
__device__ __half g_xh[MROWS * HID];
__device__ __half g_Wh[4 * HID * HID];    // Wq,Wk,Wv (6144x2048) + Wo
__device__ __half g_Qh[MROWS * HID];
__device__ __half g_Kh[MROWS * HID];
__device__ __half g_Vth[MROWS * HID];     // V^T per (b,h): [128 d][2048 s]
__device__ __half g_Ctxh[MROWS * HID];

// ---------------------------------------------------------------------------
// Helpers
// ---------------------------------------------------------------------------
__device__ __forceinline__ void mma_f16(float* c, const unsigned* a, const unsigned* b)
{
    asm volatile(
        "mma.sync.aligned.m16n8k16.row.col.f32.f16.f16.f32 "
        "{%0,%1,%2,%3}, {%4,%5,%6,%7}, {%8,%9}, {%0,%1,%2,%3};\n"
        : "+f"(c[0]), "+f"(c[1]), "+f"(c[2]), "+f"(c[3])
        : "r"(a[0]), "r"(a[1]), "r"(a[2]), "r"(a[3]),
          "r"(b[0]), "r"(b[1]));
}
__device__ __forceinline__ void ldsm_x4(unsigned* r, unsigned addr)
{
    asm volatile("ldmatrix.sync.aligned.m8n8.x4.shared.b16 {%0,%1,%2,%3}, [%4];"
                 : "=r"(r[0]), "=r"(r[1]), "=r"(r[2]), "=r"(r[3]) : "r"(addr));
}
__device__ __forceinline__ void cp_async16(unsigned saddr, const void* gaddr)
{
    asm volatile("cp.async.cg.shared.global [%0], [%1], 16;\n"
                 :: "r"(saddr), "l"(gaddr));
}
__device__ __forceinline__ void cp_commit()
{
    asm volatile("cp.async.commit_group;\n" ::: "memory");
}
__device__ __forceinline__ void cp_wait0()
{
    asm volatile("cp.async.wait_group 0;\n" ::: "memory");
}
__device__ __forceinline__ void cp_wait1()
{
    asm volatile("cp.async.wait_group 1;\n" ::: "memory");
}

// ---------------------------------------------------------------------------
// Fused fp32 -> fp16 convert: 6 regions x 1M float4
// ---------------------------------------------------------------------------
#define REG4 (1024 * 1024)

__global__ void to_half_all(const float4* __restrict__ x,
                            const float4* __restrict__ Wq,
                            const float4* __restrict__ Wk,
                            const float4* __restrict__ Wv,
                            const float4* __restrict__ Wo,
                            uint2* __restrict__ xh, uint2* __restrict__ Wh)
{
    const int region = blockIdx.y;
    const float4* src;
    uint2* dst;
    if (region == 0)      { src = x;        dst = xh; }
    else if (region == 1) { src = x + REG4; dst = xh + REG4; }
    else {
        src = (region == 2) ? Wq : (region == 3) ? Wk : (region == 4) ? Wv : Wo;
        dst = Wh + (size_t)(region - 2) * REG4;
    }
    for (int i = blockIdx.x * blockDim.x + threadIdx.x; i < REG4;
         i += gridDim.x * blockDim.x) {
        float4 v = src[i];
        __half2 h0 = __floats2half2_rn(v.x, v.y);
        __half2 h1 = __floats2half2_rn(v.z, v.w);
        uint2 u;
        u.x = *(unsigned*)&h0;
        u.y = *(unsigned*)&h1;
        dst[i] = u;
    }
}

// ---------------------------------------------------------------------------
// Pipelined FP16 GEMM: ldmatrix, cross-tile preload, COMPILE-TIME stage
// rotation (K fixed at 2048 -> 32 tiles = 10x3 + 2).
// ---------------------------------------------------------------------------
#define G3STG  3
#define G3MATW 4608
#define G3STGW 9216
#define GEMM_SMEM (G3STG * G3STGW * 4)   // 110592 B
#define NTILES 32

#define ISSUE_STAGE(st, k0) do {                                              \
    const unsigned so_ = shb + (unsigned)(st) * (G3STGW * 4);                 \
    _Pragma("unroll")                                                         \
    for (int j_ = 0; j_ < 4; j_++) {                                          \
        const int c_ = tid + 256 * j_, r_ = c_ >> 3, kq_ = c_ & 7;            \
        cp_async16(so_ + r_ * 144 + kq_ * 16,                                 \
                   Abase + (size_t)r_ * K + (k0) + kq_ * 8);                  \
        cp_async16(so_ + G3MATW * 4 + r_ * 144 + kq_ * 16,                    \
                   Bbase + (size_t)r_ * K + (k0) + kq_ * 8);                  \
    } } while (0)

#define LOAD_FRAGS(buf, stg, ko) do {                                         \
    const unsigned aB_ = shb + (unsigned)(stg) * (G3STGW * 4)                 \
                       + (unsigned)(wm + aRow) * 144 + aCol + (ko);           \
    const unsigned bB_ = shb + (unsigned)(stg) * (G3STGW * 4) + G3MATW * 4    \
                       + (unsigned)(wn + bRow) * 144 + bCol + (ko);           \
    _Pragma("unroll")                                                         \
    for (int mt_ = 0; mt_ < 4; mt_++)                                         \
        ldsm_x4(af[buf][mt_], aB_ + mt_ * (16 * 144));                        \
    _Pragma("unroll")                                                         \
    for (int pr_ = 0; pr_ < 2; pr_++)                                         \
        ldsm_x4(bf[buf][pr_], bB_ + pr_ * (16 * 144));                        \
    } while (0)

// One K-tile body with literal stage numbers. CUR = stage read, NXT = stage
// of tile ii+1 (preloaded at end), ISS = stage written for tile ii+2.
#define GBODY(CUR, NXT, ISS, ii) do {                                         \
    if ((ii) + 2 < NTILES) ISSUE_STAGE(ISS, ((ii) + 2) * 64);                 \
    cp_commit();                                                              \
    _Pragma("unroll")                                                         \
    for (int sub = 0; sub < 4; sub++) {                                       \
        const int cur = sub & 1;                                              \
        if (sub < 3) LOAD_FRAGS(cur ^ 1, CUR, (unsigned)(sub + 1) * 32);      \
        _Pragma("unroll")                                                     \
        for (int mt = 0; mt < 4; mt++)                                        \
            _Pragma("unroll")                                                 \
            for (int nt = 0; nt < 4; nt++)                                    \
                mma_f16(c[mt][nt], af[cur][mt],                               \
                        &bf[cur][nt >> 1][(nt & 1) * 2]);                     \
    }                                                                         \
    cp_wait1();                                                               \
    __syncthreads();                                                          \
    if ((ii) + 1 < NTILES) LOAD_FRAGS(0, NXT, 0);                             \
} while (0)

template<bool QKV>
__global__ __launch_bounds__(256, 2)
void gemm_f16_pipe(const __half* __restrict__ A, const __half* __restrict__ B,
                   float* __restrict__ C0,
                   __half* __restrict__ Qh, __half* __restrict__ Kh,
                   __half* __restrict__ Vth, int M, int Nout, int K)
{
    extern __shared__ unsigned sh[];

    const int tid  = threadIdx.x;
    const int lane = tid & 31;
    const int warp = tid >> 5;
    const int g    = lane >> 2;
    const int t    = lane & 3;
    const int wm   = (warp & 1) * 64;
    const int wn   = (warp >> 1) * 32;

    const int aRow      = (lane & 7) + ((lane >> 3) & 1) * 8;
    const unsigned aCol = ((lane >> 4) & 1) * 16;
    const int bRow      = (lane & 7) + ((lane >> 4) & 1) * 8;
    const unsigned bCol = ((lane >> 3) & 1) * 16;

    const __half* Abase = A + (size_t)blockIdx.y * 128 * K;
    const __half* Bbase = B + (size_t)blockIdx.x * 128 * K;
    const unsigned shb = (unsigned)__cvta_generic_to_shared(sh);

    float c[4][4][4];
#pragma unroll
    for (int i = 0; i < 4; i++)
#pragma unroll
        for (int j = 0; j < 4; j++)
#pragma unroll
            for (int q = 0; q < 4; q++) c[i][j][q] = 0.f;

    unsigned af[2][4][4], bf[2][2][4];

    ISSUE_STAGE(0, 0);  cp_commit();
    ISSUE_STAGE(1, 64); cp_commit();
    cp_wait1();
    __syncthreads();
    LOAD_FRAGS(0, 0, 0);

#pragma unroll 1
    for (int i = 0; i < 30; i += 3) {
        GBODY(0, 1, 2, i);
        GBODY(1, 2, 0, i + 1);
        GBODY(2, 0, 1, i + 2);
    }
    GBODY(0, 1, 2, 30);
    GBODY(1, 2, 0, 31);

    if (!QKV) {
        const size_t colbase = (size_t)blockIdx.x * 128;
#pragma unroll
        for (int mt = 0; mt < 4; mt++) {
            const size_t row = (size_t)blockIdx.y * 128 + wm + mt * 16 + g;
#pragma unroll
            for (int nt = 0; nt < 4; nt++) {
                const size_t col = colbase + wn + nt * 8 + 2 * t;
                *(float2*)(C0 + row * Nout + col) =
                    make_float2(c[mt][nt][0], c[mt][nt][1]);
                *(float2*)(C0 + (row + 8) * Nout + col) =
                    make_float2(c[mt][nt][2], c[mt][nt][3]);
            }
        }
        return;
    }

    __syncthreads();
    float* St = (float*)sh;        // [128][132]
#pragma unroll
    for (int mt = 0; mt < 4; mt++) {
        const int row = wm + mt * 16 + g;
#pragma unroll
        for (int nt = 0; nt < 4; nt++) {
            const int col = wn + nt * 8 + 2 * t;
            *(float2*)&St[row * 132 + col] =
                make_float2(c[mt][nt][0], c[mt][nt][1]);
            *(float2*)&St[(row + 8) * 132 + col] =
                make_float2(c[mt][nt][2], c[mt][nt][3]);
        }
    }
    __syncthreads();

    const int seg = blockIdx.x >> 4;
    const int hh  = blockIdx.x & 15;

    if (seg < 2) {
        __half* dst = (seg == 0) ? Qh : Kh;
        const bool hi = lane >= 16;
        const int l4  = (lane & 15) * 4;
#pragma unroll 4
        for (int pass = 0; pass < 16; pass++) {
            const int r    = pass * 8 + warp;
            const int grow = blockIdx.y * 128 + r;
            const int s    = grow & (S_LEN - 1);
            __half outh[4];
#pragma unroll
            for (int k = 0; k < 4; k++) {
                const int i = l4 + k;
                const float q1 = St[r * 132 + i];
                const float q2 = St[r * 132 + i + 64];
                float inv = powf(10000.0f, -((float)(2 * i)) / 128.0f);
                float sn, cs;
                sincosf((float)s * inv, &sn, &cs);
                const float v = hi ? (q1 * sn + q2 * cs) : (q1 * cs - q2 * sn);
                outh[k] = __float2half_rn(v);
            }
            const int j0 = (hi ? 64 : 0) + l4;
            *(uint2*)&dst[(size_t)grow * HID + hh * HD + j0] = *(uint2*)outh;
        }
    } else {
        const int bh = (blockIdx.y >> 4) * 16 + hh;
        const int s0 = (blockIdx.y & 15) * 128;
#pragma unroll 4
        for (int pass = 0; pass < 16; pass++) {
            const int d = pass * 8 + warp;
            __half outh[4];
#pragma unroll
            for (int k = 0; k < 4; k++)
                outh[k] = __float2half_rn(St[(lane * 4 + k) * 132 + d]);
            *(uint2*)&Vth[((size_t)bh * HD + d) * S_LEN + s0 + lane * 4] =
                *(uint2*)outh;
        }
    }
}

// ---------------------------------------------------------------------------
// Flash v2: register-resident softmax; main loop unrolled by 2 so the K/V
// stage parity (it & 1) is compile-time.
// ---------------------------------------------------------------------------
#define FK0 8704
#define FV0 17408
#define FLASH_SMEM (22016 * 4)   // 88064 B

__global__ __launch_bounds__(256, 2)
void flash_f16()
{
    extern __shared__ float sm[];

    const int tid  = threadIdx.x;
    const int lane = tid & 31;
    const int warp = tid >> 5;
    const int g    = lane >> 2;
    const int t    = lane & 3;
    const int q0   = blockIdx.x * 128;
    const int b    = blockIdx.y >> 4;
    const int h    = blockIdx.y & 15;
    const size_t base = (size_t)(b * S_LEN) * HID + (size_t)h * HD;
    const size_t vtb  = (size_t)blockIdx.y * HD * S_LEN;
    const unsigned shb = (unsigned)__cvta_generic_to_shared(sm);

    const int aRow      = (lane & 7) + ((lane >> 3) & 1) * 8;
    const unsigned aCol = ((lane >> 4) & 1) * 16;
    const int bRow      = (lane & 7) + ((lane >> 4) & 1) * 8;
    const unsigned bCol = ((lane >> 3) & 1) * 16;

    // prologue P0 = {Q, K0, V0}, P1 = {K1}
#pragma unroll
    for (int j = 0; j < 8; j++) {
        const int c = tid + 256 * j, r = c >> 4, q = c & 15;
        cp_async16(shb + r * 272 + q * 16,
                   &g_Qh[base + (size_t)(q0 + r) * HID + q * 8]);
    }
#pragma unroll
    for (int j = 0; j < 4; j++) {
        const int c = tid + 256 * j;
        const int r = c >> 4, q = c & 15;
        cp_async16(shb + FK0 * 4 + r * 272 + q * 16,
                   &g_Kh[base + (size_t)r * HID + q * 8]);
        const int r2 = c >> 3, q2 = c & 7;
        cp_async16(shb + FV0 * 4 + r2 * 144 + q2 * 16,
                   &g_Vth[vtb + (size_t)r2 * S_LEN + q2 * 8]);
    }
    cp_commit();
#pragma unroll
    for (int j = 0; j < 4; j++) {
        const int c = tid + 256 * j, r = c >> 4, q = c & 15;
        cp_async16(shb + (FK0 + 4352) * 4 + r * 272 + q * 16,
                   &g_Kh[base + (size_t)(64 + r) * HID + q * 8]);
    }
    cp_commit();

    float rmax0 = -1e30f, rmax1 = -1e30f, rsum0 = 0.f, rsum1 = 0.f;
    float o[8][2][4];
#pragma unroll
    for (int mt = 0; mt < 8; mt++)
#pragma unroll
        for (int nt = 0; nt < 2; nt++)
#pragma unroll
            for (int j = 0; j < 4; j++) o[mt][nt][j] = 0.f;

    const unsigned qB = shb + (unsigned)(16 * warp + aRow) * 272 + aCol;
    const unsigned vB = shb + FV0 * 4 + (unsigned)aRow * 144 + aCol;

    const int NT = S_LEN / 64;   // 32
#pragma unroll 2
    for (int it = 0; it < NT; it++) {
        const int s = it & 1;
        if (it == 0) { cp_wait1(); __syncthreads(); }

        const unsigned kB = shb + (FK0 + s * 4352) * 4
                          + (unsigned)bRow * 272 + bCol;

        // ---- S = Q K^T : warp tile 16q x 64k ----
        float c[8][4];
#pragma unroll
        for (int j = 0; j < 8; j++)
#pragma unroll
            for (int e = 0; e < 4; e++) c[j][e] = 0.f;

#pragma unroll
        for (int kk = 0; kk < 8; kk++) {
            unsigned aQ[4];
            ldsm_x4(aQ, qB + kk * 32);
#pragma unroll
            for (int p = 0; p < 4; p++) {
                unsigned bfr[4];
                ldsm_x4(bfr, kB + p * (16 * 272) + kk * 32);
                mma_f16(c[2 * p],     aQ, &bfr[0]);
                mma_f16(c[2 * p + 1], aQ, &bfr[2]);
            }
        }

        // ---- softmax in registers ----
        float m0 = rmax0, m1 = rmax1;
#pragma unroll
        for (int j = 0; j < 8; j++) {
            m0 = fmaxf(m0, fmaxf(c[j][0] * SCALE, c[j][1] * SCALE));
            m1 = fmaxf(m1, fmaxf(c[j][2] * SCALE, c[j][3] * SCALE));
        }
        m0 = fmaxf(m0, __shfl_xor_sync(0xffffffffu, m0, 1));
        m0 = fmaxf(m0, __shfl_xor_sync(0xffffffffu, m0, 2));
        m1 = fmaxf(m1, __shfl_xor_sync(0xffffffffu, m1, 1));
        m1 = fmaxf(m1, __shfl_xor_sync(0xffffffffu, m1, 2));
        const float a0 = __expf(rmax0 - m0);
        const float a1 = __expf(rmax1 - m1);

        unsigned pu0[8], pu1[8];
        float p0 = 0.f, p1 = 0.f;
#pragma unroll
        for (int j = 0; j < 8; j++) {
            const float e00 = __expf(c[j][0] * SCALE - m0);
            const float e01 = __expf(c[j][1] * SCALE - m0);
            p0 += e00 + e01;
            __half2 h0 = __floats2half2_rn(e00, e01);
            pu0[j] = *(unsigned*)&h0;
            const float e10 = __expf(c[j][2] * SCALE - m1);
            const float e11 = __expf(c[j][3] * SCALE - m1);
            p1 += e10 + e11;
            __half2 h1 = __floats2half2_rn(e10, e11);
            pu1[j] = *(unsigned*)&h1;
        }
        p0 += __shfl_xor_sync(0xffffffffu, p0, 1);
        p0 += __shfl_xor_sync(0xffffffffu, p0, 2);
        p1 += __shfl_xor_sync(0xffffffffu, p1, 1);
        p1 += __shfl_xor_sync(0xffffffffu, p1, 2);
        rsum0 = rsum0 * a0 + p0;  rmax0 = m0;
        rsum1 = rsum1 * a1 + p1;  rmax1 = m1;

        const float aq0 = __shfl_sync(0xffffffffu, a0, 8 * t);
        const float aq1 = __shfl_sync(0xffffffffu, a0, 8 * t + 4);
        const float aq2 = __shfl_sync(0xffffffffu, a1, 8 * t);
        const float aq3 = __shfl_sync(0xffffffffu, a1, 8 * t + 4);
#pragma unroll
        for (int mt = 0; mt < 8; mt++) {
            o[mt][0][0] *= aq0; o[mt][0][1] *= aq1;
            o[mt][0][2] *= aq0; o[mt][0][3] *= aq1;
            o[mt][1][0] *= aq2; o[mt][1][1] *= aq3;
            o[mt][1][2] *= aq2; o[mt][1][3] *= aq3;
        }

        cp_wait0();          // V(it) + K(it+1) arrived
        __syncthreads();

        if (it + 2 < NT) {
            const int kt2 = (it + 2) * 64;
#pragma unroll
            for (int j = 0; j < 4; j++) {
                const int c2 = tid + 256 * j, r = c2 >> 4, q = c2 & 15;
                cp_async16(shb + (FK0 + s * 4352) * 4 + r * 272 + q * 16,
                           &g_Kh[base + (size_t)(kt2 + r) * HID + q * 8]);
            }
        }
        cp_commit();

        // ---- O^T += V^T P^T ----
#pragma unroll
        for (int kk = 0; kk < 4; kk++) {
            unsigned bb0[2] = {pu0[2 * kk], pu0[2 * kk + 1]};
            unsigned bb1[2] = {pu1[2 * kk], pu1[2 * kk + 1]};
#pragma unroll
            for (int mt = 0; mt < 8; mt++) {
                unsigned aV[4];
                ldsm_x4(aV, vB + mt * (16 * 144) + kk * 32);
                mma_f16(o[mt][0], aV, bb0);
                mma_f16(o[mt][1], aV, bb1);
            }
        }
        __syncthreads();

        if (it + 1 < NT) {
            const int kt1 = (it + 1) * 64;
#pragma unroll
            for (int j = 0; j < 4; j++) {
                const int c2 = tid + 256 * j, r2 = c2 >> 3, q2 = c2 & 7;
                cp_async16(shb + FV0 * 4 + r2 * 144 + q2 * 16,
                           &g_Vth[vtb + (size_t)r2 * S_LEN + kt1 + q2 * 8]);
            }
        }
        cp_commit();
    }

    // ---- epilogue ----
    const float i0 = 1.0f / rsum0;
    const float i1 = 1.0f / rsum1;
    const float iq0 = __shfl_sync(0xffffffffu, i0, 8 * t);
    const float iq1 = __shfl_sync(0xffffffffu, i0, 8 * t + 4);
    const float iq2 = __shfl_sync(0xffffffffu, i1, 8 * t);
    const float iq3 = __shfl_sync(0xffffffffu, i1, 8 * t + 4);

    __syncthreads();
    __half* Ot = (__half*)sm;    // [128 d][136]
#pragma unroll
    for (int mt = 0; mt < 8; mt++) {
        const int d = mt * 16 + g;
        const int qc = warp * 16 + 2 * t;
        __half2 v;
        v = __floats2half2_rn(o[mt][0][0] * iq0, o[mt][0][1] * iq1);
        *(__half2*)&Ot[d * 136 + qc] = v;
        v = __floats2half2_rn(o[mt][0][2] * iq0, o[mt][0][3] * iq1);
        *(__half2*)&Ot[(d + 8) * 136 + qc] = v;
        v = __floats2half2_rn(o[mt][1][0] * iq2, o[mt][1][1] * iq3);
        *(__half2*)&Ot[d * 136 + qc + 8] = v;
        v = __floats2half2_rn(o[mt][1][2] * iq2, o[mt][1][3] * iq3);
        *(__half2*)&Ot[(d + 8) * 136 + qc + 8] = v;
    }
    __syncthreads();

#pragma unroll
    for (int j = 0; j < 8; j++) {
        const int c2 = tid + 256 * j;
        const int r = c2 >> 4, ch = c2 & 15;
        __half tmp[8];
#pragma unroll
        for (int i = 0; i < 8; i++)
            tmp[i] = Ot[(ch * 8 + i) * 136 + r];
        *(uint4*)&g_Ctxh[base + (size_t)(q0 + r) * HID + ch * 8] = *(uint4*)tmp;
    }
}

// ---------------------------------------------------------------------------
// Launch
// ---------------------------------------------------------------------------
extern "C" void kernel_launch(void* const* d_in, const int* in_sizes, int n_in,
                              void* d_out, int out_size)
{
    const float* x  = (const float*)d_in[0];
    const float* Wq = (const float*)d_in[1];
    const float* Wk = (const float*)d_in[2];
    const float* Wv = (const float*)d_in[3];
    const float* Wo = (const float*)d_in[4];
    float* out = (float*)d_out;

    __half *pXh, *pWh, *pQh, *pKh, *pVth, *pCh;
    cudaGetSymbolAddress((void**)&pXh,  g_xh);
    cudaGetSymbolAddress((void**)&pWh,  g_Wh);
    cudaGetSymbolAddress((void**)&pQh,  g_Qh);
    cudaGetSymbolAddress((void**)&pKh,  g_Kh);
    cudaGetSymbolAddress((void**)&pVth, g_Vth);
    cudaGetSymbolAddress((void**)&pCh,  g_Ctxh);

    const int WSZ = HID * HID;

    to_half_all<<<dim3(512, 6), 256>>>(
        (const float4*)x, (const float4*)Wq, (const float4*)Wk,
        (const float4*)Wv, (const float4*)Wo, (uint2*)pXh, (uint2*)pWh);

    cudaFuncSetAttribute(gemm_f16_pipe<true>,
                         cudaFuncAttributeMaxDynamicSharedMemorySize, GEMM_SMEM);
    cudaFuncSetAttribute(gemm_f16_pipe<false>,
                         cudaFuncAttributeMaxDynamicSharedMemorySize, GEMM_SMEM);

    gemm_f16_pipe<true><<<dim3(48, MROWS / 128), 256, GEMM_SMEM>>>(
        pXh, pWh, nullptr, pQh, pKh, pVth, MROWS, HID, HID);

    cudaFuncSetAttribute(flash_f16,
                         cudaFuncAttributeMaxDynamicSharedMemorySize, FLASH_SMEM);
    flash_f16<<<dim3(S_LEN / 128, 2 * NHEAD), 256, FLASH_SMEM>>>();

    gemm_f16_pipe<false><<<dim3(16, MROWS / 128), 256, GEMM_SMEM>>>(
        pCh, pWh + 3 * WSZ, out, nullptr, nullptr, nullptr, MROWS, HID, HID);
}

// round 17
// speedup vs baseline: 1.0625x; 1.0625x over previous
#include <cuda_runtime.h>
#include <cuda_fp16.h>
#include <math.h>

#define S_LEN 2048
#define HID   2048
#define NHEAD 16
#define HD    128
#define MROWS 4096
#define SCALE 0.08838834764831845f

// ---------------------------------------------------------------------------
// Global scratch
// ---------------------------------------------------------------------------
__device__ __half g_xh[MROWS * HID];
__device__ __half g_Wh[4 * HID * HID];    // Wq,Wk,Wv (6144x2048) + Wo
__device__ __half g_Qh[MROWS * HID];
__device__ __half g_Kh[MROWS * HID];
__device__ __half g_Vth[MROWS * HID];     // V^T per (b,h): [128 d][2048 s]
__device__ __half g_Ctxh[MROWS * HID];
__device__ float2 g_RT[S_LEN * 64];       // RoPE (cos, sin) table

// ---------------------------------------------------------------------------
// Helpers
// ---------------------------------------------------------------------------
__device__ __forceinline__ void mma_f16(float* c, const unsigned* a, const unsigned* b)
{
    asm volatile(
        "mma.sync.aligned.m16n8k16.row.col.f32.f16.f16.f32 "
        "{%0,%1,%2,%3}, {%4,%5,%6,%7}, {%8,%9}, {%0,%1,%2,%3};\n"
        : "+f"(c[0]), "+f"(c[1]), "+f"(c[2]), "+f"(c[3])
        : "r"(a[0]), "r"(a[1]), "r"(a[2]), "r"(a[3]),
          "r"(b[0]), "r"(b[1]));
}
__device__ __forceinline__ void ldsm_x4(unsigned* r, unsigned addr)
{
    asm volatile("ldmatrix.sync.aligned.m8n8.x4.shared.b16 {%0,%1,%2,%3}, [%4];"
                 : "=r"(r[0]), "=r"(r[1]), "=r"(r[2]), "=r"(r[3]) : "r"(addr));
}
__device__ __forceinline__ void cp_async16(unsigned saddr, const void* gaddr)
{
    asm volatile("cp.async.cg.shared.global [%0], [%1], 16;\n"
                 :: "r"(saddr), "l"(gaddr));
}
__device__ __forceinline__ void cp_commit()
{
    asm volatile("cp.async.commit_group;\n" ::: "memory");
}
__device__ __forceinline__ void cp_wait0()
{
    asm volatile("cp.async.wait_group 0;\n" ::: "memory");
}
__device__ __forceinline__ void cp_wait1()
{
    asm volatile("cp.async.wait_group 1;\n" ::: "memory");
}

// ---------------------------------------------------------------------------
// RoPE table: identical float expressions to the old in-epilogue math.
// ---------------------------------------------------------------------------
__global__ void rope_table_kernel()
{
    const int idx = blockIdx.x * blockDim.x + threadIdx.x;   // s*64 + i
    if (idx >= S_LEN * 64) return;
    const int s = idx >> 6;
    const int i = idx & 63;
    float inv = powf(10000.0f, -((float)(2 * i)) / 128.0f);
    float sn, cs;
    sincosf((float)s * inv, &sn, &cs);
    g_RT[idx] = make_float2(cs, sn);
}

// ---------------------------------------------------------------------------
// Fused fp32 -> fp16 convert: 6 regions x 1M float4
// ---------------------------------------------------------------------------
#define REG4 (1024 * 1024)

__global__ void to_half_all(const float4* __restrict__ x,
                            const float4* __restrict__ Wq,
                            const float4* __restrict__ Wk,
                            const float4* __restrict__ Wv,
                            const float4* __restrict__ Wo,
                            uint2* __restrict__ xh, uint2* __restrict__ Wh)
{
    const int region = blockIdx.y;
    const float4* src;
    uint2* dst;
    if (region == 0)      { src = x;        dst = xh; }
    else if (region == 1) { src = x + REG4; dst = xh + REG4; }
    else {
        src = (region == 2) ? Wq : (region == 3) ? Wk : (region == 4) ? Wv : Wo;
        dst = Wh + (size_t)(region - 2) * REG4;
    }
    for (int i = blockIdx.x * blockDim.x + threadIdx.x; i < REG4;
         i += gridDim.x * blockDim.x) {
        float4 v = src[i];
        __half2 h0 = __floats2half2_rn(v.x, v.y);
        __half2 h1 = __floats2half2_rn(v.z, v.w);
        uint2 u;
        u.x = *(unsigned*)&h0;
        u.y = *(unsigned*)&h1;
        dst[i] = u;
    }
}

// ---------------------------------------------------------------------------
// Pipelined FP16 GEMM, ldmatrix + cross-tile sub0 fragment preload (R15 form:
// runtime stage index, single rolled loop).
// ---------------------------------------------------------------------------
#define G3STG  3
#define G3MATW 4608
#define G3STGW 9216
#define GEMM_SMEM (G3STG * G3STGW * 4)   // 110592 B

#define ISSUE_STAGE(st, k0) do {                                              \
    const unsigned so_ = shb + (unsigned)(st) * (G3STGW * 4);                 \
    _Pragma("unroll")                                                         \
    for (int j_ = 0; j_ < 4; j_++) {                                          \
        const int c_ = tid + 256 * j_, r_ = c_ >> 3, kq_ = c_ & 7;            \
        cp_async16(so_ + r_ * 144 + kq_ * 16,                                 \
                   Abase + (size_t)r_ * K + (k0) + kq_ * 8);                  \
        cp_async16(so_ + G3MATW * 4 + r_ * 144 + kq_ * 16,                    \
                   Bbase + (size_t)r_ * K + (k0) + kq_ * 8);                  \
    } } while (0)

#define LOAD_FRAGS(buf, stg, ko) do {                                         \
    const unsigned aB_ = shb + (unsigned)(stg) * (G3STGW * 4)                 \
                       + (unsigned)(wm + aRow) * 144 + aCol + (ko);           \
    const unsigned bB_ = shb + (unsigned)(stg) * (G3STGW * 4) + G3MATW * 4    \
                       + (unsigned)(wn + bRow) * 144 + bCol + (ko);           \
    _Pragma("unroll")                                                         \
    for (int mt_ = 0; mt_ < 4; mt_++)                                         \
        ldsm_x4(af[buf][mt_], aB_ + mt_ * (16 * 144));                        \
    _Pragma("unroll")                                                         \
    for (int pr_ = 0; pr_ < 2; pr_++)                                         \
        ldsm_x4(bf[buf][pr_], bB_ + pr_ * (16 * 144));                        \
    } while (0)

template<bool QKV>
__global__ __launch_bounds__(256, 2)
void gemm_f16_pipe(const __half* __restrict__ A, const __half* __restrict__ B,
                   float* __restrict__ C0,
                   __half* __restrict__ Qh, __half* __restrict__ Kh,
                   __half* __restrict__ Vth, int M, int Nout, int K)
{
    extern __shared__ unsigned sh[];

    const int tid  = threadIdx.x;
    const int lane = tid & 31;
    const int warp = tid >> 5;
    const int g    = lane >> 2;
    const int t    = lane & 3;
    const int wm   = (warp & 1) * 64;
    const int wn   = (warp >> 1) * 32;

    const int aRow      = (lane & 7) + ((lane >> 3) & 1) * 8;
    const unsigned aCol = ((lane >> 4) & 1) * 16;
    const int bRow      = (lane & 7) + ((lane >> 4) & 1) * 8;
    const unsigned bCol = ((lane >> 3) & 1) * 16;

    const __half* Abase = A + (size_t)blockIdx.y * 128 * K;
    const __half* Bbase = B + (size_t)blockIdx.x * 128 * K;
    const unsigned shb = (unsigned)__cvta_generic_to_shared(sh);

    const int ntiles = K / 64;

    float c[4][4][4];
#pragma unroll
    for (int i = 0; i < 4; i++)
#pragma unroll
        for (int j = 0; j < 4; j++)
#pragma unroll
            for (int q = 0; q < 4; q++) c[i][j][q] = 0.f;

    unsigned af[2][4][4], bf[2][2][4];

    ISSUE_STAGE(0, 0);  cp_commit();
    ISSUE_STAGE(1, 64); cp_commit();
    cp_wait1();
    __syncthreads();                 // stage 0 ready + visible to all
    LOAD_FRAGS(0, 0, 0);             // preload sub0 frags of tile 0

    for (int i = 0; i < ntiles; i++) {
        const int stg = i % 3;

        if (i + 2 < ntiles) ISSUE_STAGE((i + 2) % 3, (i + 2) * 64);
        cp_commit();

#pragma unroll
        for (int sub = 0; sub < 4; sub++) {
            const int cur = sub & 1;
            if (sub < 3) LOAD_FRAGS(cur ^ 1, stg, (unsigned)(sub + 1) * 32);
#pragma unroll
            for (int mt = 0; mt < 4; mt++)
#pragma unroll
                for (int nt = 0; nt < 4; nt++)
                    mma_f16(c[mt][nt], af[cur][mt], &bf[cur][nt >> 1][(nt & 1) * 2]);
        }

        cp_wait1();
        __syncthreads();
        if (i + 1 < ntiles) LOAD_FRAGS(0, (i + 1) % 3, 0);
    }

    if (!QKV) {
        const size_t colbase = (size_t)blockIdx.x * 128;
#pragma unroll
        for (int mt = 0; mt < 4; mt++) {
            const size_t row = (size_t)blockIdx.y * 128 + wm + mt * 16 + g;
#pragma unroll
            for (int nt = 0; nt < 4; nt++) {
                const size_t col = colbase + wn + nt * 8 + 2 * t;
                *(float2*)(C0 + row * Nout + col) =
                    make_float2(c[mt][nt][0], c[mt][nt][1]);
                *(float2*)(C0 + (row + 8) * Nout + col) =
                    make_float2(c[mt][nt][2], c[mt][nt][3]);
            }
        }
        return;
    }

    __syncthreads();
    float* St = (float*)sh;        // [128][132]
#pragma unroll
    for (int mt = 0; mt < 4; mt++) {
        const int row = wm + mt * 16 + g;
#pragma unroll
        for (int nt = 0; nt < 4; nt++) {
            const int col = wn + nt * 8 + 2 * t;
            *(float2*)&St[row * 132 + col] =
                make_float2(c[mt][nt][0], c[mt][nt][1]);
            *(float2*)&St[(row + 8) * 132 + col] =
                make_float2(c[mt][nt][2], c[mt][nt][3]);
        }
    }
    __syncthreads();

    const int seg = blockIdx.x >> 4;
    const int hh  = blockIdx.x & 15;

    if (seg < 2) {
        // RoPE via precomputed table (identical arithmetic)
        __half* dst = (seg == 0) ? Qh : Kh;
        const bool hi = lane >= 16;
        const int l4  = (lane & 15) * 4;
#pragma unroll 4
        for (int pass = 0; pass < 16; pass++) {
            const int r    = pass * 8 + warp;
            const int grow = blockIdx.y * 128 + r;
            const int s    = grow & (S_LEN - 1);
            __half outh[4];
#pragma unroll
            for (int k = 0; k < 4; k++) {
                const int i = l4 + k;
                const float q1 = St[r * 132 + i];
                const float q2 = St[r * 132 + i + 64];
                const float2 cssn = g_RT[s * 64 + i];
                const float cs = cssn.x, sn = cssn.y;
                const float v = hi ? (q1 * sn + q2 * cs) : (q1 * cs - q2 * sn);
                outh[k] = __float2half_rn(v);
            }
            const int j0 = (hi ? 64 : 0) + l4;
            *(uint2*)&dst[(size_t)grow * HID + hh * HD + j0] = *(uint2*)outh;
        }
    } else {
        const int bh = (blockIdx.y >> 4) * 16 + hh;
        const int s0 = (blockIdx.y & 15) * 128;
#pragma unroll 4
        for (int pass = 0; pass < 16; pass++) {
            const int d = pass * 8 + warp;
            __half outh[4];
#pragma unroll
            for (int k = 0; k < 4; k++)
                outh[k] = __float2half_rn(St[(lane * 4 + k) * 132 + d]);
            *(uint2*)&Vth[((size_t)bh * HD + d) * S_LEN + s0 + lane * 4] =
                *(uint2*)outh;
        }
    }
}

// ---------------------------------------------------------------------------
// Flash v2: register-resident softmax (R15 form).
// ---------------------------------------------------------------------------
#define FK0 8704
#define FV0 17408
#define FLASH_SMEM (22016 * 4)   // 88064 B

__global__ __launch_bounds__(256, 2)
void flash_f16()
{
    extern __shared__ float sm[];

    const int tid  = threadIdx.x;
    const int lane = tid & 31;
    const int warp = tid >> 5;
    const int g    = lane >> 2;
    const int t    = lane & 3;
    const int q0   = blockIdx.x * 128;
    const int b    = blockIdx.y >> 4;
    const int h    = blockIdx.y & 15;
    const size_t base = (size_t)(b * S_LEN) * HID + (size_t)h * HD;
    const size_t vtb  = (size_t)blockIdx.y * HD * S_LEN;
    const unsigned shb = (unsigned)__cvta_generic_to_shared(sm);

    const int aRow      = (lane & 7) + ((lane >> 3) & 1) * 8;
    const unsigned aCol = ((lane >> 4) & 1) * 16;
    const int bRow      = (lane & 7) + ((lane >> 4) & 1) * 8;
    const unsigned bCol = ((lane >> 3) & 1) * 16;

    // prologue P0 = {Q, K0, V0}, P1 = {K1}
#pragma unroll
    for (int j = 0; j < 8; j++) {
        const int c = tid + 256 * j, r = c >> 4, q = c & 15;
        cp_async16(shb + r * 272 + q * 16,
                   &g_Qh[base + (size_t)(q0 + r) * HID + q * 8]);
    }
#pragma unroll
    for (int j = 0; j < 4; j++) {
        const int c = tid + 256 * j;
        const int r = c >> 4, q = c & 15;
        cp_async16(shb + FK0 * 4 + r * 272 + q * 16,
                   &g_Kh[base + (size_t)r * HID + q * 8]);
        const int r2 = c >> 3, q2 = c & 7;
        cp_async16(shb + FV0 * 4 + r2 * 144 + q2 * 16,
                   &g_Vth[vtb + (size_t)r2 * S_LEN + q2 * 8]);
    }
    cp_commit();
#pragma unroll
    for (int j = 0; j < 4; j++) {
        const int c = tid + 256 * j, r = c >> 4, q = c & 15;
        cp_async16(shb + (FK0 + 4352) * 4 + r * 272 + q * 16,
                   &g_Kh[base + (size_t)(64 + r) * HID + q * 8]);
    }
    cp_commit();

    float rmax0 = -1e30f, rmax1 = -1e30f, rsum0 = 0.f, rsum1 = 0.f;
    float o[8][2][4];
#pragma unroll
    for (int mt = 0; mt < 8; mt++)
#pragma unroll
        for (int nt = 0; nt < 2; nt++)
#pragma unroll
            for (int j = 0; j < 4; j++) o[mt][nt][j] = 0.f;

    const unsigned qB = shb + (unsigned)(16 * warp + aRow) * 272 + aCol;
    const unsigned vB = shb + FV0 * 4 + (unsigned)aRow * 144 + aCol;

    const int NT = S_LEN / 64;   // 32
    for (int it = 0; it < NT; it++) {
        const int s = it & 1;
        if (it == 0) { cp_wait1(); __syncthreads(); }

        const unsigned kB = shb + (FK0 + s * 4352) * 4
                          + (unsigned)bRow * 272 + bCol;

        // ---- S = Q K^T : warp tile 16q x 64k ----
        float c[8][4];
#pragma unroll
        for (int j = 0; j < 8; j++)
#pragma unroll
            for (int e = 0; e < 4; e++) c[j][e] = 0.f;

#pragma unroll
        for (int kk = 0; kk < 8; kk++) {
            unsigned aQ[4];
            ldsm_x4(aQ, qB + kk * 32);
#pragma unroll
            for (int p = 0; p < 4; p++) {
                unsigned bfr[4];
                ldsm_x4(bfr, kB + p * (16 * 272) + kk * 32);
                mma_f16(c[2 * p],     aQ, &bfr[0]);
                mma_f16(c[2 * p + 1], aQ, &bfr[2]);
            }
        }

        // ---- softmax in registers ----
        float m0 = rmax0, m1 = rmax1;
#pragma unroll
        for (int j = 0; j < 8; j++) {
            m0 = fmaxf(m0, fmaxf(c[j][0] * SCALE, c[j][1] * SCALE));
            m1 = fmaxf(m1, fmaxf(c[j][2] * SCALE, c[j][3] * SCALE));
        }
        m0 = fmaxf(m0, __shfl_xor_sync(0xffffffffu, m0, 1));
        m0 = fmaxf(m0, __shfl_xor_sync(0xffffffffu, m0, 2));
        m1 = fmaxf(m1, __shfl_xor_sync(0xffffffffu, m1, 1));
        m1 = fmaxf(m1, __shfl_xor_sync(0xffffffffu, m1, 2));
        const float a0 = __expf(rmax0 - m0);
        const float a1 = __expf(rmax1 - m1);

        unsigned pu0[8], pu1[8];
        float p0 = 0.f, p1 = 0.f;
#pragma unroll
        for (int j = 0; j < 8; j++) {
            const float e00 = __expf(c[j][0] * SCALE - m0);
            const float e01 = __expf(c[j][1] * SCALE - m0);
            p0 += e00 + e01;
            __half2 h0 = __floats2half2_rn(e00, e01);
            pu0[j] = *(unsigned*)&h0;
            const float e10 = __expf(c[j][2] * SCALE - m1);
            const float e11 = __expf(c[j][3] * SCALE - m1);
            p1 += e10 + e11;
            __half2 h1 = __floats2half2_rn(e10, e11);
            pu1[j] = *(unsigned*)&h1;
        }
        p0 += __shfl_xor_sync(0xffffffffu, p0, 1);
        p0 += __shfl_xor_sync(0xffffffffu, p0, 2);
        p1 += __shfl_xor_sync(0xffffffffu, p1, 1);
        p1 += __shfl_xor_sync(0xffffffffu, p1, 2);
        rsum0 = rsum0 * a0 + p0;  rmax0 = m0;
        rsum1 = rsum1 * a1 + p1;  rmax1 = m1;

        const float aq0 = __shfl_sync(0xffffffffu, a0, 8 * t);
        const float aq1 = __shfl_sync(0xffffffffu, a0, 8 * t + 4);
        const float aq2 = __shfl_sync(0xffffffffu, a1, 8 * t);
        const float aq3 = __shfl_sync(0xffffffffu, a1, 8 * t + 4);
#pragma unroll
        for (int mt = 0; mt < 8; mt++) {
            o[mt][0][0] *= aq0; o[mt][0][1] *= aq1;
            o[mt][0][2] *= aq0; o[mt][0][3] *= aq1;
            o[mt][1][0] *= aq2; o[mt][1][1] *= aq3;
            o[mt][1][2] *= aq2; o[mt][1][3] *= aq3;
        }

        cp_wait0();          // V(it) + K(it+1) arrived
        __syncthreads();

        if (it + 2 < NT) {
            const int kt2 = (it + 2) * 64;
#pragma unroll
            for (int j = 0; j < 4; j++) {
                const int c2 = tid + 256 * j, r = c2 >> 4, q = c2 & 15;
                cp_async16(shb + (FK0 + s * 4352) * 4 + r * 272 + q * 16,
                           &g_Kh[base + (size_t)(kt2 + r) * HID + q * 8]);
            }
        }
        cp_commit();

        // ---- O^T += V^T P^T ----
#pragma unroll
        for (int kk = 0; kk < 4; kk++) {
            unsigned bb0[2] = {pu0[2 * kk], pu0[2 * kk + 1]};
            unsigned bb1[2] = {pu1[2 * kk], pu1[2 * kk + 1]};
#pragma unroll
            for (int mt = 0; mt < 8; mt++) {
                unsigned aV[4];
                ldsm_x4(aV, vB + mt * (16 * 144) + kk * 32);
                mma_f16(o[mt][0], aV, bb0);
                mma_f16(o[mt][1], aV, bb1);
            }
        }
        __syncthreads();

        if (it + 1 < NT) {
            const int kt1 = (it + 1) * 64;
#pragma unroll
            for (int j = 0; j < 4; j++) {
                const int c2 = tid + 256 * j, r2 = c2 >> 3, q2 = c2 & 7;
                cp_async16(shb + FV0 * 4 + r2 * 144 + q2 * 16,
                           &g_Vth[vtb + (size_t)r2 * S_LEN + kt1 + q2 * 8]);
            }
        }
        cp_commit();
    }

    // ---- epilogue ----
    const float i0 = 1.0f / rsum0;
    const float i1 = 1.0f / rsum1;
    const float iq0 = __shfl_sync(0xffffffffu, i0, 8 * t);
    const float iq1 = __shfl_sync(0xffffffffu, i0, 8 * t + 4);
    const float iq2 = __shfl_sync(0xffffffffu, i1, 8 * t);
    const float iq3 = __shfl_sync(0xffffffffu, i1, 8 * t + 4);

    __syncthreads();
    __half* Ot = (__half*)sm;    // [128 d][136]
#pragma unroll
    for (int mt = 0; mt < 8; mt++) {
        const int d = mt * 16 + g;
        const int qc = warp * 16 + 2 * t;
        __half2 v;
        v = __floats2half2_rn(o[mt][0][0] * iq0, o[mt][0][1] * iq1);
        *(__half2*)&Ot[d * 136 + qc] = v;
        v = __floats2half2_rn(o[mt][0][2] * iq0, o[mt][0][3] * iq1);
        *(__half2*)&Ot[(d + 8) * 136 + qc] = v;
        v = __floats2half2_rn(o[mt][1][0] * iq2, o[mt][1][1] * iq3);
        *(__half2*)&Ot[d * 136 + qc + 8] = v;
        v = __floats2half2_rn(o[mt][1][2] * iq2, o[mt][1][3] * iq3);
        *(__half2*)&Ot[(d + 8) * 136 + qc + 8] = v;
    }
    __syncthreads();

#pragma unroll
    for (int j = 0; j < 8; j++) {
        const int c2 = tid + 256 * j;
        const int r = c2 >> 4, ch = c2 & 15;
        __half tmp[8];
#pragma unroll
        for (int i = 0; i < 8; i++)
            tmp[i] = Ot[(ch * 8 + i) * 136 + r];
        *(uint4*)&g_Ctxh[base + (size_t)(q0 + r) * HID + ch * 8] = *(uint4*)tmp;
    }
}

// ---------------------------------------------------------------------------
// Launch
// ---------------------------------------------------------------------------
extern "C" void kernel_launch(void* const* d_in, const int* in_sizes, int n_in,
                              void* d_out, int out_size)
{
    const float* x  = (const float*)d_in[0];
    const float* Wq = (const float*)d_in[1];
    const float* Wk = (const float*)d_in[2];
    const float* Wv = (const float*)d_in[3];
    const float* Wo = (const float*)d_in[4];
    float* out = (float*)d_out;

    __half *pXh, *pWh, *pQh, *pKh, *pVth, *pCh;
    cudaGetSymbolAddress((void**)&pXh,  g_xh);
    cudaGetSymbolAddress((void**)&pWh,  g_Wh);
    cudaGetSymbolAddress((void**)&pQh,  g_Qh);
    cudaGetSymbolAddress((void**)&pKh,  g_Kh);
    cudaGetSymbolAddress((void**)&pVth, g_Vth);
    cudaGetSymbolAddress((void**)&pCh,  g_Ctxh);

    const int WSZ = HID * HID;

    rope_table_kernel<<<S_LEN * 64 / 256, 256>>>();
    to_half_all<<<dim3(512, 6), 256>>>(
        (const float4*)x, (const float4*)Wq, (const float4*)Wk,
        (const float4*)Wv, (const float4*)Wo, (uint2*)pXh, (uint2*)pWh);

    cudaFuncSetAttribute(gemm_f16_pipe<true>,
                         cudaFuncAttributeMaxDynamicSharedMemorySize, GEMM_SMEM);
    cudaFuncSetAttribute(gemm_f16_pipe<false>,
                         cudaFuncAttributeMaxDynamicSharedMemorySize, GEMM_SMEM);

    gemm_f16_pipe<true><<<dim3(48, MROWS / 128), 256, GEMM_SMEM>>>(
        pXh, pWh, nullptr, pQh, pKh, pVth, MROWS, HID, HID);

    cudaFuncSetAttribute(flash_f16,
                         cudaFuncAttributeMaxDynamicSharedMemorySize, FLASH_SMEM);
    flash_f16<<<dim3(S_LEN / 128, 2 * NHEAD), 256, FLASH_SMEM>>>();

    gemm_f16_pipe<false><<<dim3(16, MROWS / 128), 256, GEMM_SMEM>>>(
        pCh, pWh + 3 * WSZ, out, nullptr, nullptr, nullptr, MROWS, HID, HID);
}